// round 16
// baseline (speedup 1.0000x reference)
#include <cuda_runtime.h>
#include <cuda_fp16.h>
#include <cstdint>

// ---------------- problem constants ----------------
#define B_    32
#define L_    336
#define C_    321
#define P_    96
#define E_    4
#define H_    2048
#define PATCH 12
#define NROW  (B_*C_)          // 10272
#define KTOT  (E_*H_)          // 8192
#define NSPL  8
#define INV_  0.99999499987499937f   // 1/sqrt(1+1e-5)

// ---------------- scratch (static device globals; no allocation) ----------------
__device__ float  g_h  [NROW*L_];
__device__ float  g_s2 [NROW*168];
__device__ float  g_s4 [NROW*84];
__device__ float  g_s8 [NROW*42];
__device__ float  g_t  [NROW*168];
__device__ float  g_cur[NROW*L_];
__device__ float  g_te [NROW*L_];
__device__ __half g_ddih[NROW*L_];             // fp16 ddi
__device__ __half g_w1h[E_*H_*L_];             // fp16 ew1 (5.5 MB)
__device__ float  g_gates[NROW*E_];
__device__ __half g_hid[(size_t)NROW*KTOT];    // 168 MB fp16
__device__ __half g_w2p[P_*KTOT];              // repacked fp16 ew2
__device__ float  g_part[(size_t)NSPL*NROW*P_];// 31.5 MB split-K partials

__device__ __forceinline__ float gelu_f(float x) {
    return 0.5f * x * (1.0f + erff(x * 0.70710678118654752f));
}

// ---------------- mma helpers ----------------
__device__ __forceinline__ uint32_t f2tf32(float x) {
    uint32_t r;
    asm("cvt.rna.tf32.f32 %0, %1;" : "=r"(r) : "f"(x));
    return r;
}
__device__ __forceinline__ void mma_tf32(float* c, const uint32_t* a, const uint32_t* b) {
    asm volatile(
        "mma.sync.aligned.m16n8k8.row.col.f32.tf32.tf32.f32 "
        "{%0,%1,%2,%3}, {%4,%5,%6,%7}, {%8,%9}, {%0,%1,%2,%3};"
        : "+f"(c[0]), "+f"(c[1]), "+f"(c[2]), "+f"(c[3])
        : "r"(a[0]), "r"(a[1]), "r"(a[2]), "r"(a[3]), "r"(b[0]), "r"(b[1]));
}
__device__ __forceinline__ void mma_f16(float* c, const uint32_t* a, const uint32_t* b) {
    asm volatile(
        "mma.sync.aligned.m16n8k16.row.col.f32.f16.f16.f32 "
        "{%0,%1,%2,%3}, {%4,%5,%6,%7}, {%8,%9}, {%0,%1,%2,%3};"
        : "+f"(c[0]), "+f"(c[1]), "+f"(c[2]), "+f"(c[3])
        : "r"(a[0]), "r"(a[1]), "r"(a[2]), "r"(a[3]), "r"(b[0]), "r"(b[1]));
}
__device__ __forceinline__ void ldsm_x4(uint32_t& r0, uint32_t& r1, uint32_t& r2, uint32_t& r3,
                                        uint32_t saddr) {
    asm volatile("ldmatrix.sync.aligned.m8n8.x4.shared.b16 {%0,%1,%2,%3}, [%4];"
                 : "=r"(r0), "=r"(r1), "=r"(r2), "=r"(r3) : "r"(saddr));
}
__device__ __forceinline__ uint32_t smem_u32(const void* p) {
    return (uint32_t)__cvta_generic_to_shared(p);
}
__device__ __forceinline__ void cp_async16(void* smem, const void* gmem, int bytes) {
    uint32_t saddr = smem_u32(smem);
    asm volatile("cp.async.ca.shared.global [%0], [%1], 16, %2;"
                 :: "r"(saddr), "l"(gmem), "r"(bytes));
}
__device__ __forceinline__ void cp_commit() { asm volatile("cp.async.commit_group;"); }
template<int N> __device__ __forceinline__ void cp_wait() {
    asm volatile("cp.async.wait_group %0;" :: "n"(N));
}

// ================= expert layer-1: fp16 m16n8k16 GEMM, 3-stage pipeline =================
__global__ void __launch_bounds__(256) gemm_f16_l1(
    const __half* __restrict__ A,     // NROW x 336
    const __half* __restrict__ W1,    // (E, 2048, 336)
    const float* __restrict__ eb1,    // (E, 2048)
    const float* __restrict__ gates,  // (NROW, 4)
    __half* __restrict__ hid,         // NROW x 8192
    int M)
{
    constexpr int KK = L_;
    constexpr int NK = KK / 16;       // 21
    __shared__ __align__(16) __half As[3][128][24];
    __shared__ __align__(16) __half Ws[3][128][24];

    int tid = threadIdx.x;
    int e   = blockIdx.z;
    const __half* W   = W1 + (size_t)e * H_ * KK;
    const float* bias = eb1 + (size_t)e * H_;
    int rowBase = blockIdx.y * 128;
    int colBase = blockIdx.x * 128;
    int lane = tid & 31, warp = tid >> 5;
    int g = lane >> 2, t4 = lane & 3;
    int wm0 = (warp >> 1) * 32, wn0 = (warp & 1) * 64;

    uint32_t aBase[3] = { smem_u32(&As[0][0][0]), smem_u32(&As[1][0][0]), smem_u32(&As[2][0][0]) };
    uint32_t bBase[3] = { smem_u32(&Ws[0][0][0]), smem_u32(&Ws[1][0][0]), smem_u32(&Ws[2][0][0]) };
    uint32_t aOff = (uint32_t)(((wm0 + (lane & 15)) * 24 + ((lane >> 4) << 3)) * 2);
    uint32_t bOff = (uint32_t)(((wn0 + (lane & 7) + ((lane >> 4) << 3)) * 24
                               + (((lane >> 3) & 1) << 3)) * 2);

    float acc[2][8][4];
    #pragma unroll
    for (int i = 0; i < 2; i++)
        #pragma unroll
        for (int j = 0; j < 8; j++)
            #pragma unroll
            for (int q = 0; q < 4; q++) acc[i][j][q] = 0.f;

    auto load_tile = [&](int it, int s) {
        int k0 = it * 16;
        int r = tid >> 1, j = tid & 1;
        int gm = rowBase + r;
        int gmc = gm < M ? gm : (M - 1);
        cp_async16(&As[s][r][j * 8],
                   A + (size_t)gmc * KK + k0 + j * 8,
                   gm < M ? 16 : 0);
        cp_async16(&Ws[s][r][j * 8],
                   W + (size_t)(colBase + r) * KK + k0 + j * 8, 16);
        cp_commit();
    };

    load_tile(0, 0);
    load_tile(1, 1);
    for (int it = 0; it < NK; it++) {
        int s = it % 3;
        if (it + 1 < NK) cp_wait<1>(); else cp_wait<0>();
        __syncthreads();
        if (it + 2 < NK) load_tile(it + 2, (it + 2) % 3);
        {
            uint32_t afr[2][4], bfr[8][2];
            #pragma unroll
            for (int mt = 0; mt < 2; mt++)
                ldsm_x4(afr[mt][0], afr[mt][1], afr[mt][2], afr[mt][3],
                        aBase[s] + aOff + (uint32_t)(mt * 768));
            #pragma unroll
            for (int np = 0; np < 4; np++)
                ldsm_x4(bfr[2 * np][0], bfr[2 * np][1], bfr[2 * np + 1][0], bfr[2 * np + 1][1],
                        bBase[s] + bOff + (uint32_t)(np * 768));
            #pragma unroll
            for (int mt = 0; mt < 2; mt++)
                #pragma unroll
                for (int nt = 0; nt < 8; nt++)
                    mma_f16(acc[mt][nt], afr[mt], bfr[nt]);
        }
    }

    #pragma unroll
    for (int mt = 0; mt < 2; mt++) {
        int r0 = rowBase + wm0 + mt * 16 + g;
        int r1 = r0 + 8;
        float g0 = (r0 < M) ? gates[r0 * 4 + e] : 0.f;
        float g1 = (r1 < M) ? gates[r1 * 4 + e] : 0.f;
        #pragma unroll
        for (int nt = 0; nt < 8; nt++) {
            int c0 = colBase + wn0 + nt * 8 + 2 * t4;
            float b0v = bias[c0], b1v = bias[c0 + 1];
            if (r0 < M) {
                __half2* p = (__half2*)(hid + (size_t)r0 * KTOT + (size_t)e * H_ + c0);
                *p = __floats2half2_rn(gelu_f(acc[mt][nt][0] + b0v) * g0,
                                       gelu_f(acc[mt][nt][1] + b1v) * g0);
            }
            if (r1 < M) {
                __half2* p = (__half2*)(hid + (size_t)r1 * KTOT + (size_t)e * H_ + c0);
                *p = __floats2half2_rn(gelu_f(acc[mt][nt][2] + b0v) * g1,
                                       gelu_f(acc[mt][nt][3] + b1v) * g1);
            }
        }
    }
}

// ================= expert layer-2: fp16 split-K GEMM -> split buffers (no atomics) =================
__global__ void __launch_bounds__(256) gemm_f16_l2(
    const __half* __restrict__ A,    // NROW x 8192 (g_hid)
    const __half* __restrict__ W,    // 96 x 8192 (g_w2p)
    float* __restrict__ part,        // (NSPL, NROW, 96)
    int M)
{
    constexpr int KC = KTOT / NSPL;   // 1024
    constexpr int NK = KC / 16;       // 64
    __shared__ __align__(16) __half As[3][128][24];
    __shared__ __align__(16) __half Ws[3][96][24];

    int tid = threadIdx.x;
    int rowBase = blockIdx.y * 128;
    int kBase = blockIdx.z * KC;
    int lane = tid & 31, warp = tid >> 5;
    int g = lane >> 2, t4 = lane & 3;
    int wm0 = (warp >> 1) * 32, wn0 = (warp & 1) * 48;

    uint32_t aBase[3] = { smem_u32(&As[0][0][0]), smem_u32(&As[1][0][0]), smem_u32(&As[2][0][0]) };
    uint32_t bBase[3] = { smem_u32(&Ws[0][0][0]), smem_u32(&Ws[1][0][0]), smem_u32(&Ws[2][0][0]) };
    uint32_t aOff = (uint32_t)(((wm0 + (lane & 15)) * 24 + ((lane >> 4) << 3)) * 2);
    uint32_t bOff = (uint32_t)(((wn0 + (lane & 7) + ((lane >> 4) << 3)) * 24
                               + (((lane >> 3) & 1) << 3)) * 2);

    float acc[2][6][4];
    #pragma unroll
    for (int i = 0; i < 2; i++)
        #pragma unroll
        for (int j = 0; j < 6; j++)
            #pragma unroll
            for (int q = 0; q < 4; q++) acc[i][j][q] = 0.f;

    auto load_tile = [&](int it, int s) {
        int k0 = kBase + it * 16;
        int r = tid >> 1, j = tid & 1;
        int gm = rowBase + r;
        int gmc = gm < M ? gm : (M - 1);
        cp_async16(&As[s][r][j * 8],
                   A + (size_t)gmc * KTOT + k0 + j * 8,
                   gm < M ? 16 : 0);
        if (r < 96)
            cp_async16(&Ws[s][r][j * 8],
                       W + (size_t)r * KTOT + k0 + j * 8, 16);
        cp_commit();
    };

    load_tile(0, 0);
    load_tile(1, 1);
    for (int it = 0; it < NK; it++) {
        int s = it % 3;
        if (it + 1 < NK) cp_wait<1>(); else cp_wait<0>();
        __syncthreads();
        if (it + 2 < NK) load_tile(it + 2, (it + 2) % 3);
        {
            uint32_t afr[2][4], bfr[6][2];
            #pragma unroll
            for (int mt = 0; mt < 2; mt++)
                ldsm_x4(afr[mt][0], afr[mt][1], afr[mt][2], afr[mt][3],
                        aBase[s] + aOff + (uint32_t)(mt * 768));
            #pragma unroll
            for (int np = 0; np < 3; np++)
                ldsm_x4(bfr[2 * np][0], bfr[2 * np][1], bfr[2 * np + 1][0], bfr[2 * np + 1][1],
                        bBase[s] + bOff + (uint32_t)(np * 768));
            #pragma unroll
            for (int mt = 0; mt < 2; mt++)
                #pragma unroll
                for (int nt = 0; nt < 6; nt++)
                    mma_f16(acc[mt][nt], afr[mt], bfr[nt]);
        }
    }

    float* pz = part + (size_t)blockIdx.z * NROW * P_;
    #pragma unroll
    for (int mt = 0; mt < 2; mt++) {
        #pragma unroll
        for (int hh = 0; hh < 2; hh++) {
            int gm = rowBase + wm0 + mt * 16 + g + hh * 8;
            if (gm >= M) continue;
            float* prow = pz + (size_t)gm * P_;
            #pragma unroll
            for (int nt = 0; nt < 6; nt++) {
                int c0 = wn0 + nt * 8 + 2 * t4;
                prow[c0]     = acc[mt][nt][hh * 2];
                prow[c0 + 1] = acc[mt][nt][hh * 2 + 1];
            }
        }
    }
}

// ---------------- reduce split-K partials + gated bias -> Out (B,96,C) ----------------
__global__ void reduce_l2_kernel(const float* __restrict__ part,
                                 const float* __restrict__ eb2,
                                 const float* __restrict__ gates,
                                 float* __restrict__ Out)
{
    int idx = blockIdx.x * blockDim.x + threadIdx.x;
    if (idx >= NROW * P_) return;
    int gm = idx / P_, gn = idx % P_;
    float v = 0.f;
    #pragma unroll
    for (int z = 0; z < NSPL; z++)
        v += part[(size_t)z * NROW * P_ + idx];
    float bsum = 0.f;
    #pragma unroll
    for (int ee = 0; ee < E_; ee++)
        bsum += gates[gm * 4 + ee] * eb2[ee * P_ + gn];
    int bb = gm / C_, cc = gm % C_;
    Out[((size_t)bb * P_ + gn) * C_ + cc] = v + bsum;
}

// ---------------- bn + transpose ----------------
__global__ void bn_transpose_kernel(const float* __restrict__ x,
                                    const float* __restrict__ w,
                                    const float* __restrict__ b,
                                    float* __restrict__ h)
{
    __shared__ float tile[32][33];
    int bi = blockIdx.z;
    int l0 = blockIdx.x * 32;
    int c0 = blockIdx.y * 32;
    int tx = threadIdx.x, ty = threadIdx.y;   // 32 x 8
    #pragma unroll
    for (int i = 0; i < 32; i += 8) {
        int l = l0 + ty + i, c = c0 + tx;
        tile[ty + i][tx] = (l < L_ && c < C_) ? x[((size_t)bi * L_ + l) * C_ + c] : 0.f;
    }
    __syncthreads();
    #pragma unroll
    for (int i = 0; i < 32; i += 8) {
        int c = c0 + ty + i, l = l0 + tx;
        if (c < C_ && l < L_) {
            float v = tile[tx][ty + i];
            int wi = c * L_ + l;
            h[((size_t)bi * C_ + c) * L_ + l] = v * (w[wi] * INV_) + b[wi];
        }
    }
}

// ---------------- fused pool: h -> s2, s4, s8 in one pass ----------------
__global__ void pool_all_kernel(const float* __restrict__ h,
                                float* __restrict__ s2,
                                float* __restrict__ s4,
                                float* __restrict__ s8)
{
    int idx = blockIdx.x * blockDim.x + threadIdx.x;
    if (idx >= NROW * 42) return;
    int r = idx / 42, j = idx % 42;
    const float* p = h + (size_t)r * L_ + j * 8;
    float a0 = 0.5f * (p[0] + p[1]);
    float a1 = 0.5f * (p[2] + p[3]);
    float a2 = 0.5f * (p[4] + p[5]);
    float a3 = 0.5f * (p[6] + p[7]);
    float b0 = 0.5f * (a0 + a1);
    float b1 = 0.5f * (a2 + a3);
    float* q2 = s2 + (size_t)r * 168 + j * 4;
    q2[0] = a0; q2[1] = a1; q2[2] = a2; q2[3] = a3;
    float* q4 = s4 + (size_t)r * 84 + j * 2;
    q4[0] = b0; q4[1] = b1;
    s8[(size_t)r * 42 + j] = 0.5f * (b0 + b1);
}

// ---------------- mixer fp32 GEMM, BM=64 x BN=64 (stages 1-2, K=42) ----------------
template<int ACT>
__global__ void __launch_bounds__(256) gemm_m(
    const float* __restrict__ A, int lda,
    const float* __restrict__ W,
    const float* __restrict__ bias,
    const float* __restrict__ resid,
    float* __restrict__ Cout, int ldc,
    int M, int N, int K)
{
    constexpr int BM = 64, BN = 64, BK = 16, TM = 4, TN = 4;
    __shared__ __align__(16) float As[BK][BM + 4];
    __shared__ __align__(16) float Ws[BK][BN + 4];
    int tid = threadIdx.x;
    int ty = tid >> 4, tx = tid & 15;
    int rowBase = blockIdx.y * BM, colBase = blockIdx.x * BN;
    float acc[TM][TN] = {};

    for (int k0 = 0; k0 < K; k0 += BK) {
        #pragma unroll
        for (int i = 0; i < 4; i++) {
            int idx = tid + 256 * i;
            int m = idx >> 4, kk = idx & 15;
            int gk = k0 + kk;
            int gm = rowBase + m;
            As[kk][m] = (gm < M && gk < K) ? A[(size_t)gm * lda + gk] : 0.f;
            int gn = colBase + m;
            Ws[kk][m] = (gn < N && gk < K) ? W[(size_t)gn * K + gk] : 0.f;
        }
        __syncthreads();
        #pragma unroll
        for (int kk = 0; kk < BK; kk++) {
            float a[TM], bf[TN];
            *(float4*)&a[0]  = *(const float4*)&As[kk][ty * TM];
            *(float4*)&bf[0] = *(const float4*)&Ws[kk][tx * TN];
            #pragma unroll
            for (int i = 0; i < TM; i++)
                #pragma unroll
                for (int j = 0; j < TN; j++)
                    acc[i][j] += a[i] * bf[j];
        }
        __syncthreads();
    }

    #pragma unroll
    for (int i = 0; i < TM; i++) {
        int gm = rowBase + ty * TM + i;
        if (gm >= M) continue;
        #pragma unroll
        for (int j = 0; j < TN; j++) {
            int gn = colBase + tx * TN + j;
            if (gn >= N) continue;
            float v = acc[i][j] + (bias ? bias[gn] : 0.f);
            if (ACT == 1) v = gelu_f(v);
            if (resid) v += resid[(size_t)gm * N + gn];
            Cout[(size_t)gm * ldc + gn] = v;
        }
    }
}

// ---------------- mixer tf32 tensor-core GEMM, BM=64 x BN=64 (stages 3-6) ----------------
template<int ACT>
__global__ void __launch_bounds__(256) gemm_tc_m(
    const float* __restrict__ A, int lda,
    const float* __restrict__ W,
    const float* __restrict__ bias,
    const float* __restrict__ resid,
    float* __restrict__ Cout, int ldc,
    int M, int N, int K)
{
    __shared__ __align__(16) float As[2][64][20];
    __shared__ __align__(16) float Ws[2][64][20];
    int tid = threadIdx.x, lane = tid & 31, warp = tid >> 5;
    int g = lane >> 2, t4 = lane & 3;
    int wm = (warp >> 1) * 16, wn = (warp & 1) * 32;
    int rowBase = blockIdx.y * 64, colBase = blockIdx.x * 64;

    float acc[4][4];
    #pragma unroll
    for (int i = 0; i < 4; i++)
        #pragma unroll
        for (int q = 0; q < 4; q++) acc[i][q] = 0.f;

    auto load_tile = [&](int it, int buf) {
        int k0 = it * 16;
        int r = tid >> 2, j = tid & 3;
        int kf = k0 + j * 4;
        int kok = (kf + 4 <= K);
        int kfc = kok ? kf : 0;
        int gm = rowBase + r;
        int gmc = gm < M ? gm : (M - 1);
        cp_async16(&As[buf][r][j * 4],
                   A + (size_t)gmc * lda + kfc,
                   (gm < M && kok) ? 16 : 0);
        int gn = colBase + r;
        int gnc = gn < N ? gn : (N - 1);
        cp_async16(&Ws[buf][r][j * 4],
                   W + (size_t)gnc * K + kfc,
                   (gn < N && kok) ? 16 : 0);
        cp_commit();
    };

    int NK = (K + 15) >> 4;
    int buf = 0;
    load_tile(0, 0);
    for (int it = 0; it < NK; it++) {
        if (it + 1 < NK) { load_tile(it + 1, buf ^ 1); cp_wait<1>(); }
        else             { cp_wait<0>(); }
        __syncthreads();
        #pragma unroll
        for (int kk = 0; kk < 16; kk += 8) {
            uint32_t afr[4], bfr[4][2];
            afr[0] = f2tf32(As[buf][wm + g    ][kk + t4]);
            afr[1] = f2tf32(As[buf][wm + g + 8][kk + t4]);
            afr[2] = f2tf32(As[buf][wm + g    ][kk + t4 + 4]);
            afr[3] = f2tf32(As[buf][wm + g + 8][kk + t4 + 4]);
            #pragma unroll
            for (int nt = 0; nt < 4; nt++) {
                int cb = wn + nt * 8 + g;
                bfr[nt][0] = f2tf32(Ws[buf][cb][kk + t4]);
                bfr[nt][1] = f2tf32(Ws[buf][cb][kk + t4 + 4]);
            }
            #pragma unroll
            for (int nt = 0; nt < 4; nt++)
                mma_tf32(acc[nt], afr, bfr[nt]);
        }
        __syncthreads();
        buf ^= 1;
    }

    int r0 = rowBase + wm + g;
    int r1 = r0 + 8;
    #pragma unroll
    for (int nt = 0; nt < 4; nt++) {
        int c0 = colBase + wn + nt * 8 + 2 * t4;
        #pragma unroll
        for (int q = 0; q < 2; q++) {
            int gn = c0 + q;
            if (gn >= N) continue;
            if (r0 < M) {
                float v = acc[nt][q] + (bias ? bias[gn] : 0.f);
                if (ACT == 1) v = gelu_f(v);
                if (resid) v += resid[(size_t)r0 * N + gn];
                Cout[(size_t)r0 * ldc + gn] = v;
            }
            if (r1 < M) {
                float v = acc[nt][2 + q] + (bias ? bias[gn] : 0.f);
                if (ACT == 1) v = gelu_f(v);
                if (resid) v += resid[(size_t)r1 * N + gn];
                Cout[(size_t)r1 * ldc + gn] = v;
            }
        }
    }
}

// ---------------- gating ----------------
__global__ void gate_kernel(const float* __restrict__ te,
                            const float* __restrict__ gw,
                            const float* __restrict__ gb,
                            float* __restrict__ gates)
{
    int warp = (blockIdx.x * blockDim.x + threadIdx.x) >> 5;
    int lane = threadIdx.x & 31;
    if (warp >= NROW) return;
    const float* row = te + (size_t)warp * L_;
    float acc[E_] = {0.f, 0.f, 0.f, 0.f};
    for (int l = lane; l < L_; l += 32) {
        float xv = row[l];
        #pragma unroll
        for (int e = 0; e < E_; e++) acc[e] += xv * gw[e * L_ + l];
    }
    #pragma unroll
    for (int off = 16; off; off >>= 1)
        #pragma unroll
        for (int e = 0; e < E_; e++)
            acc[e] += __shfl_xor_sync(0xffffffffu, acc[e], off);
    if (lane == 0) {
        float lg[E_], arr[E_];
        #pragma unroll
        for (int e = 0; e < E_; e++) { lg[e] = acc[e] + gb[e]; arr[e] = lg[e]; }
        #pragma unroll
        for (int i = 0; i < 3; i++)
            #pragma unroll
            for (int j = 0; j < 3; j++)
                if (arr[j] > arr[j + 1]) { float tmp = arr[j]; arr[j] = arr[j + 1]; arr[j + 1] = tmp; }
        float kth = arr[E_ - 2];
        float mx = lg[0];
        #pragma unroll
        for (int e = 1; e < E_; e++) mx = fmaxf(mx, lg[e]);
        float s[E_], ssum = 0.f;
        #pragma unroll
        for (int e = 0; e < E_; e++) { s[e] = expf(lg[e] - mx); ssum += s[e]; }
        #pragma unroll
        for (int e = 0; e < E_; e++) s[e] /= ssum;
        float dec[E_];
        #pragma unroll
        for (int e = 0; e < E_; e++)
            dec[e] = (lg[e] < kth) ? 10.f * logf(s[e] + 1.f) : 10.f * (expf(s[e]) - 1.f);
        float m2 = dec[0];
        #pragma unroll
        for (int e = 1; e < E_; e++) m2 = fmaxf(m2, dec[e]);
        float t2[E_], su = 0.f;
        #pragma unroll
        for (int e = 0; e < E_; e++) { t2[e] = expf(dec[e] - m2); su += t2[e]; }
        #pragma unroll
        for (int e = 0; e < E_; e++) gates[(size_t)warp * E_ + e] = t2[e] / su;
    }
}

// ---------------- fused bn + ddi scan, 16 lanes per row (12 active) ----------------
__global__ void __launch_bounds__(256) ddi_scan2_kernel(
    const float* __restrict__ te,
    const float* __restrict__ ddw,
    const float* __restrict__ ddb,
    const float* __restrict__ n1w,
    const float* __restrict__ n1b,
    const float* __restrict__ agg_w,
    const float* __restrict__ agg_b,
    __half* __restrict__ out)
{
    __shared__ float aw[PATCH * PATCH];
    __shared__ float ab[PATCH];
    for (int i = threadIdx.x; i < PATCH * PATCH; i += blockDim.x) aw[i] = agg_w[i];
    for (int i = threadIdx.x; i < PATCH; i += blockDim.x) ab[i] = agg_b[i];
    __syncthreads();

    int gid  = blockIdx.x * blockDim.x + threadIdx.x;
    int row  = gid >> 4;
    int lp   = gid & 15;
    if (row >= NROW) return;
    int c = row % C_;
    int base16 = (threadIdx.x & 31) & ~15;

    bool act = lp < PATCH;
    int lpc = act ? lp : 0;

    float w1 = n1w[c * PATCH + lpc] * INV_;
    float b1 = n1b[c * PATCH + lpc];

    const float* terow = te + (size_t)row * L_;
    const float* wrow  = ddw + (size_t)c * L_;
    const float* brow  = ddb + (size_t)c * L_;
    __half* orow = out + (size_t)row * L_;

    float prev = terow[lpc] * (wrow[lpc] * INV_) + brow[lpc];
    if (act) orow[lp] = __float2half_rn(prev);

    for (int t = 1; t < L_ / PATCH; t++) {
        float inp = prev * w1 + b1;
        float s = ab[lpc];
        #pragma unroll
        for (int p = 0; p < PATCH; p++) {
            float v = __shfl_sync(0xffffffffu, inp, base16 + p, 32);
            s += v * aw[lpc * PATCH + p];
        }
        float tmp = gelu_f(s);
        int l = t * PATCH + lpc;
        prev = tmp + terow[l] * (wrow[l] * INV_) + brow[l];
        if (act) orow[l] = __float2half_rn(prev);
    }
}

// ---------------- merged prep: f2h(ew1) + repack(ew2) ----------------
#define N_W1 (E_*H_*L_)      // 2752512
#define N_W2 (P_*KTOT)       // 786432
__global__ void prep_kernel(const float* __restrict__ ew1, __half* __restrict__ w1h,
                            const float* __restrict__ ew2, __half* __restrict__ w2p)
{
    int idx = blockIdx.x * blockDim.x + threadIdx.x;
    if (idx < N_W1) {
        w1h[idx] = __float2half_rn(ew1[idx]);
    }
    int i2 = idx - N_W1;
    if (i2 >= 0 && i2 < N_W2) {
        int p = i2 / KTOT;
        int r = i2 % KTOT;
        int e = r / H_, hh = r % H_;
        w2p[i2] = __float2half_rn(ew2[((size_t)e * P_ + p) * H_ + hh]);
    }
}

// ---------------- launch ----------------
extern "C" void kernel_launch(void* const* d_in, const int* in_sizes, int n_in,
                              void* d_out, int out_size)
{
    // Map inputs, skipping the scalar 'k' (size 1) wherever it sits.
    const float* in[27];
    int pi = 0;
    for (int i = 0; i < n_in && pi < 27; i++) {
        if (in_sizes[i] == 1) continue;
        in[pi++] = (const float*)d_in[i];
    }
    const float* x    = in[0];
    const float* mdw  = in[1];  const float* mdb  = in[2];
    const float* w1s[3] = { in[3], in[7],  in[11] };
    const float* b1s[3] = { in[4], in[8],  in[12] };
    const float* w2s[3] = { in[5], in[9],  in[13] };
    const float* b2s[3] = { in[6], in[10], in[14] };
    const float* ddw  = in[15]; const float* ddb  = in[16];
    const float* n1w  = in[17]; const float* n1b  = in[18];
    const float* aggw = in[19]; const float* aggb = in[20];
    const float* gw   = in[21]; const float* gb   = in[22];
    const float* ew1  = in[23]; const float* eb1  = in[24];
    const float* ew2  = in[25]; const float* eb2  = in[26];

    float *h, *s2, *s4, *s8, *t, *cur, *te, *gates, *part;
    __half *ddih, *w1h, *hid, *w2p;
    cudaGetSymbolAddress((void**)&h,    g_h);
    cudaGetSymbolAddress((void**)&s2,   g_s2);
    cudaGetSymbolAddress((void**)&s4,   g_s4);
    cudaGetSymbolAddress((void**)&s8,   g_s8);
    cudaGetSymbolAddress((void**)&t,    g_t);
    cudaGetSymbolAddress((void**)&cur,  g_cur);
    cudaGetSymbolAddress((void**)&te,   g_te);
    cudaGetSymbolAddress((void**)&ddih, g_ddih);
    cudaGetSymbolAddress((void**)&w1h,  g_w1h);
    cudaGetSymbolAddress((void**)&gates,g_gates);
    cudaGetSymbolAddress((void**)&hid,  g_hid);
    cudaGetSymbolAddress((void**)&w2p,  g_w2p);
    cudaGetSymbolAddress((void**)&part, g_part);

    float* out = (float*)d_out;

    // 0) merged prep (weights only; out is fully written by reduce)
    {
        int total = N_W1 + N_W2;
        prep_kernel<<<(total + 255) / 256, 256>>>(ew1, w1h, ew2, w2p);
    }

    // 1) bn + transpose -> h (B,C,L)
    {
        dim3 tb(32, 8);
        dim3 tg((L_ + 31) / 32, (C_ + 31) / 32, B_);
        bn_transpose_kernel<<<tg, tb>>>(x, mdw, mdb, h);
    }
    // 2) fused pools
    pool_all_kernel<<<(NROW * 42 + 255) / 256, 256>>>(h, s2, s4, s8);

    // 3) mixer: stages 1-2 fp32, stages 3-6 tf32 tensor cores
    auto mgrid = [](int M, int N) { return dim3((N + 63) / 64, (M + 63) / 64); };
    gemm_m<1>   <<<mgrid(NROW, 42), 256>>>(s8, 42, w1s[0], b1s[0], nullptr, t,   42,  NROW, 42,  42);
    gemm_m<0>   <<<mgrid(NROW, 84), 256>>>(t,  42, w2s[0], b2s[0], s4,      cur, 84,  NROW, 84,  42);
    gemm_tc_m<1><<<mgrid(NROW, 84), 256>>>(cur,84, w1s[1], b1s[1], nullptr, t,   84,  NROW, 84,  84);
    gemm_tc_m<0><<<mgrid(NROW,168), 256>>>(t,  84, w2s[1], b2s[1], s2,      cur, 168, NROW, 168, 84);
    gemm_tc_m<1><<<mgrid(NROW,168), 256>>>(cur,168,w1s[2], b1s[2], nullptr, t,   168, NROW, 168, 168);
    gemm_tc_m<0><<<mgrid(NROW,336), 256>>>(t,  168,w2s[2], b2s[2], h,       te,  336, NROW, 336, 168);

    // 4) gating from te
    gate_kernel<<<(NROW * 32 + 255) / 256, 256>>>(te, gw, gb, gates);

    // 5) fused bn + scan (16 lanes/row), emits fp16 ddi
    ddi_scan2_kernel<<<(NROW * 16 + 255) / 256, 256>>>(te, ddw, ddb, n1w, n1b, aggw, aggb, ddih);

    // 6) experts — l1, then split-buffer l2, then reduce
    {
        dim3 tg(H_ / 128, (NROW + 127) / 128, E_);
        gemm_f16_l1<<<tg, 256>>>(ddih, w1h, eb1, gates, hid, NROW);
    }
    {
        dim3 tg(1, (NROW + 127) / 128, NSPL);
        gemm_f16_l2<<<tg, 256>>>(hid, w2p, part, NROW);
    }
    reduce_l2_kernel<<<(NROW * P_ + 255) / 256, 256>>>(part, eb2, gates, out);
}

// round 17
// speedup vs baseline: 1.0561x; 1.0561x over previous
#include <cuda_runtime.h>
#include <cuda_fp16.h>
#include <cstdint>

// ---------------- problem constants ----------------
#define B_    32
#define L_    336
#define C_    321
#define P_    96
#define E_    4
#define H_    2048
#define PATCH 12
#define NROW  (B_*C_)          // 10272
#define KTOT  (E_*H_)          // 8192
#define INV_  0.99999499987499937f   // 1/sqrt(1+1e-5)

// ---------------- scratch (static device globals; no allocation) ----------------
__device__ float  g_h  [NROW*L_];
__device__ float  g_s2 [NROW*168];
__device__ float  g_s4 [NROW*84];
__device__ float  g_s8 [NROW*42];
__device__ float  g_t  [NROW*168];
__device__ float  g_cur[NROW*L_];
__device__ float  g_te [NROW*L_];
__device__ __half g_ddih[NROW*L_];             // fp16 ddi
__device__ __half g_w1h[E_*H_*L_];             // fp16 ew1 (5.5 MB)
__device__ float  g_gates[NROW*E_];
__device__ __half g_hid[(size_t)NROW*KTOT];    // 168 MB fp16
__device__ __half g_w2p[P_*KTOT];              // repacked fp16 ew2

__device__ __forceinline__ float gelu_f(float x) {
    return 0.5f * x * (1.0f + erff(x * 0.70710678118654752f));
}

// ---------------- mma helpers ----------------
__device__ __forceinline__ uint32_t f2tf32(float x) {
    uint32_t r;
    asm("cvt.rna.tf32.f32 %0, %1;" : "=r"(r) : "f"(x));
    return r;
}
__device__ __forceinline__ void mma_tf32(float* c, const uint32_t* a, const uint32_t* b) {
    asm volatile(
        "mma.sync.aligned.m16n8k8.row.col.f32.tf32.tf32.f32 "
        "{%0,%1,%2,%3}, {%4,%5,%6,%7}, {%8,%9}, {%0,%1,%2,%3};"
        : "+f"(c[0]), "+f"(c[1]), "+f"(c[2]), "+f"(c[3])
        : "r"(a[0]), "r"(a[1]), "r"(a[2]), "r"(a[3]), "r"(b[0]), "r"(b[1]));
}
__device__ __forceinline__ void mma_f16(float* c, const uint32_t* a, const uint32_t* b) {
    asm volatile(
        "mma.sync.aligned.m16n8k16.row.col.f32.f16.f16.f32 "
        "{%0,%1,%2,%3}, {%4,%5,%6,%7}, {%8,%9}, {%0,%1,%2,%3};"
        : "+f"(c[0]), "+f"(c[1]), "+f"(c[2]), "+f"(c[3])
        : "r"(a[0]), "r"(a[1]), "r"(a[2]), "r"(a[3]), "r"(b[0]), "r"(b[1]));
}
__device__ __forceinline__ void ldsm_x4(uint32_t& r0, uint32_t& r1, uint32_t& r2, uint32_t& r3,
                                        uint32_t saddr) {
    asm volatile("ldmatrix.sync.aligned.m8n8.x4.shared.b16 {%0,%1,%2,%3}, [%4];"
                 : "=r"(r0), "=r"(r1), "=r"(r2), "=r"(r3) : "r"(saddr));
}
__device__ __forceinline__ uint32_t smem_u32(const void* p) {
    return (uint32_t)__cvta_generic_to_shared(p);
}
__device__ __forceinline__ void cp_async16(void* smem, const void* gmem, int bytes) {
    uint32_t saddr = smem_u32(smem);
    asm volatile("cp.async.ca.shared.global [%0], [%1], 16, %2;"
                 :: "r"(saddr), "l"(gmem), "r"(bytes));
}
__device__ __forceinline__ void cp_commit() { asm volatile("cp.async.commit_group;"); }
template<int N> __device__ __forceinline__ void cp_wait() {
    asm volatile("cp.async.wait_group %0;" :: "n"(N));
}

// ================= expert layer-1: fp16 m16n8k16 GEMM, 3-stage pipeline =================
__global__ void __launch_bounds__(256) gemm_f16_l1(
    const __half* __restrict__ A,     // NROW x 336
    const __half* __restrict__ W1,    // (E, 2048, 336)
    const float* __restrict__ eb1,    // (E, 2048)
    const float* __restrict__ gates,  // (NROW, 4)
    __half* __restrict__ hid,         // NROW x 8192
    int M)
{
    constexpr int KK = L_;
    constexpr int NK = KK / 16;       // 21
    __shared__ __align__(16) __half As[3][128][24];
    __shared__ __align__(16) __half Ws[3][128][24];

    int tid = threadIdx.x;
    int e   = blockIdx.z;
    const __half* W   = W1 + (size_t)e * H_ * KK;
    const float* bias = eb1 + (size_t)e * H_;
    int rowBase = blockIdx.y * 128;
    int colBase = blockIdx.x * 128;
    int lane = tid & 31, warp = tid >> 5;
    int g = lane >> 2, t4 = lane & 3;
    int wm0 = (warp >> 1) * 32, wn0 = (warp & 1) * 64;

    uint32_t aBase[3] = { smem_u32(&As[0][0][0]), smem_u32(&As[1][0][0]), smem_u32(&As[2][0][0]) };
    uint32_t bBase[3] = { smem_u32(&Ws[0][0][0]), smem_u32(&Ws[1][0][0]), smem_u32(&Ws[2][0][0]) };
    uint32_t aOff = (uint32_t)(((wm0 + (lane & 15)) * 24 + ((lane >> 4) << 3)) * 2);
    uint32_t bOff = (uint32_t)(((wn0 + (lane & 7) + ((lane >> 4) << 3)) * 24
                               + (((lane >> 3) & 1) << 3)) * 2);

    float acc[2][8][4];
    #pragma unroll
    for (int i = 0; i < 2; i++)
        #pragma unroll
        for (int j = 0; j < 8; j++)
            #pragma unroll
            for (int q = 0; q < 4; q++) acc[i][j][q] = 0.f;

    auto load_tile = [&](int it, int s) {
        int k0 = it * 16;
        int r = tid >> 1, j = tid & 1;
        int gm = rowBase + r;
        int gmc = gm < M ? gm : (M - 1);
        cp_async16(&As[s][r][j * 8],
                   A + (size_t)gmc * KK + k0 + j * 8,
                   gm < M ? 16 : 0);
        cp_async16(&Ws[s][r][j * 8],
                   W + (size_t)(colBase + r) * KK + k0 + j * 8, 16);
        cp_commit();
    };

    load_tile(0, 0);
    load_tile(1, 1);
    for (int it = 0; it < NK; it++) {
        int s = it % 3;
        if (it + 1 < NK) cp_wait<1>(); else cp_wait<0>();
        __syncthreads();
        if (it + 2 < NK) load_tile(it + 2, (it + 2) % 3);
        {
            uint32_t afr[2][4], bfr[8][2];
            #pragma unroll
            for (int mt = 0; mt < 2; mt++)
                ldsm_x4(afr[mt][0], afr[mt][1], afr[mt][2], afr[mt][3],
                        aBase[s] + aOff + (uint32_t)(mt * 768));
            #pragma unroll
            for (int np = 0; np < 4; np++)
                ldsm_x4(bfr[2 * np][0], bfr[2 * np][1], bfr[2 * np + 1][0], bfr[2 * np + 1][1],
                        bBase[s] + bOff + (uint32_t)(np * 768));
            #pragma unroll
            for (int mt = 0; mt < 2; mt++)
                #pragma unroll
                for (int nt = 0; nt < 8; nt++)
                    mma_f16(acc[mt][nt], afr[mt], bfr[nt]);
        }
    }

    #pragma unroll
    for (int mt = 0; mt < 2; mt++) {
        int r0 = rowBase + wm0 + mt * 16 + g;
        int r1 = r0 + 8;
        float g0 = (r0 < M) ? gates[r0 * 4 + e] : 0.f;
        float g1 = (r1 < M) ? gates[r1 * 4 + e] : 0.f;
        #pragma unroll
        for (int nt = 0; nt < 8; nt++) {
            int c0 = colBase + wn0 + nt * 8 + 2 * t4;
            float b0v = bias[c0], b1v = bias[c0 + 1];
            if (r0 < M) {
                __half2* p = (__half2*)(hid + (size_t)r0 * KTOT + (size_t)e * H_ + c0);
                *p = __floats2half2_rn(gelu_f(acc[mt][nt][0] + b0v) * g0,
                                       gelu_f(acc[mt][nt][1] + b1v) * g0);
            }
            if (r1 < M) {
                __half2* p = (__half2*)(hid + (size_t)r1 * KTOT + (size_t)e * H_ + c0);
                *p = __floats2half2_rn(gelu_f(acc[mt][nt][2] + b0v) * g1,
                                       gelu_f(acc[mt][nt][3] + b1v) * g1);
            }
        }
    }
}

// ================= expert layer-2: fp16 split-K(16) GEMM, atomic epilogue =================
__global__ void __launch_bounds__(256) gemm_f16_l2(
    const __half* __restrict__ A,    // NROW x 8192 (g_hid)
    const __half* __restrict__ W,    // 96 x 8192 (g_w2p)
    const float* __restrict__ eb2,   // (4,96)
    const float* __restrict__ gates, // (NROW,4)
    float* __restrict__ Out,         // (B,96,C)
    int M)
{
    constexpr int NSPLIT = 16, KC = KTOT / NSPLIT;   // 512
    constexpr int NK = KC / 16;                       // 32
    __shared__ __align__(16) __half As[3][128][24];
    __shared__ __align__(16) __half Ws[3][96][24];

    int tid = threadIdx.x;
    int rowBase = blockIdx.y * 128;
    int kBase = blockIdx.z * KC;
    int lane = tid & 31, warp = tid >> 5;
    int g = lane >> 2, t4 = lane & 3;
    int wm0 = (warp >> 1) * 32, wn0 = (warp & 1) * 48;

    uint32_t aBase[3] = { smem_u32(&As[0][0][0]), smem_u32(&As[1][0][0]), smem_u32(&As[2][0][0]) };
    uint32_t bBase[3] = { smem_u32(&Ws[0][0][0]), smem_u32(&Ws[1][0][0]), smem_u32(&Ws[2][0][0]) };
    uint32_t aOff = (uint32_t)(((wm0 + (lane & 15)) * 24 + ((lane >> 4) << 3)) * 2);
    uint32_t bOff = (uint32_t)(((wn0 + (lane & 7) + ((lane >> 4) << 3)) * 24
                               + (((lane >> 3) & 1) << 3)) * 2);

    float acc[2][6][4];
    #pragma unroll
    for (int i = 0; i < 2; i++)
        #pragma unroll
        for (int j = 0; j < 6; j++)
            #pragma unroll
            for (int q = 0; q < 4; q++) acc[i][j][q] = 0.f;

    auto load_tile = [&](int it, int s) {
        int k0 = kBase + it * 16;
        int r = tid >> 1, j = tid & 1;
        int gm = rowBase + r;
        int gmc = gm < M ? gm : (M - 1);
        cp_async16(&As[s][r][j * 8],
                   A + (size_t)gmc * KTOT + k0 + j * 8,
                   gm < M ? 16 : 0);
        if (r < 96)
            cp_async16(&Ws[s][r][j * 8],
                       W + (size_t)r * KTOT + k0 + j * 8, 16);
        cp_commit();
    };

    load_tile(0, 0);
    load_tile(1, 1);
    for (int it = 0; it < NK; it++) {
        int s = it % 3;
        if (it + 1 < NK) cp_wait<1>(); else cp_wait<0>();
        __syncthreads();
        if (it + 2 < NK) load_tile(it + 2, (it + 2) % 3);
        {
            uint32_t afr[2][4], bfr[6][2];
            #pragma unroll
            for (int mt = 0; mt < 2; mt++)
                ldsm_x4(afr[mt][0], afr[mt][1], afr[mt][2], afr[mt][3],
                        aBase[s] + aOff + (uint32_t)(mt * 768));
            #pragma unroll
            for (int np = 0; np < 3; np++)
                ldsm_x4(bfr[2 * np][0], bfr[2 * np][1], bfr[2 * np + 1][0], bfr[2 * np + 1][1],
                        bBase[s] + bOff + (uint32_t)(np * 768));
            #pragma unroll
            for (int mt = 0; mt < 2; mt++)
                #pragma unroll
                for (int nt = 0; nt < 6; nt++)
                    mma_f16(acc[mt][nt], afr[mt], bfr[nt]);
        }
    }

    #pragma unroll
    for (int mt = 0; mt < 2; mt++) {
        int rr[2] = { rowBase + wm0 + mt * 16 + g, rowBase + wm0 + mt * 16 + g + 8 };
        #pragma unroll
        for (int hh = 0; hh < 2; hh++) {
            int gm = rr[hh];
            if (gm >= M) continue;
            int bb = gm / C_, cc = gm % C_;
            #pragma unroll
            for (int nt = 0; nt < 6; nt++) {
                int c0 = wn0 + nt * 8 + 2 * t4;
                #pragma unroll
                for (int q = 0; q < 2; q++) {
                    int gn = c0 + q;
                    float v = acc[mt][nt][hh * 2 + q];
                    if (blockIdx.z == 0) {
                        float bsum = 0.f;
                        #pragma unroll
                        for (int ee = 0; ee < E_; ee++)
                            bsum += gates[gm * 4 + ee] * eb2[ee * P_ + gn];
                        v += bsum;
                    }
                    atomicAdd(&Out[((size_t)bb * P_ + gn) * C_ + cc], v);
                }
            }
        }
    }
}

// ---------------- bn + transpose ----------------
__global__ void bn_transpose_kernel(const float* __restrict__ x,
                                    const float* __restrict__ w,
                                    const float* __restrict__ b,
                                    float* __restrict__ h)
{
    __shared__ float tile[32][33];
    int bi = blockIdx.z;
    int l0 = blockIdx.x * 32;
    int c0 = blockIdx.y * 32;
    int tx = threadIdx.x, ty = threadIdx.y;   // 32 x 8
    #pragma unroll
    for (int i = 0; i < 32; i += 8) {
        int l = l0 + ty + i, c = c0 + tx;
        tile[ty + i][tx] = (l < L_ && c < C_) ? x[((size_t)bi * L_ + l) * C_ + c] : 0.f;
    }
    __syncthreads();
    #pragma unroll
    for (int i = 0; i < 32; i += 8) {
        int c = c0 + ty + i, l = l0 + tx;
        if (c < C_ && l < L_) {
            float v = tile[tx][ty + i];
            int wi = c * L_ + l;
            h[((size_t)bi * C_ + c) * L_ + l] = v * (w[wi] * INV_) + b[wi];
        }
    }
}

// ---------------- fused pool: h -> s2, s4, s8 in one pass ----------------
__global__ void pool_all_kernel(const float* __restrict__ h,
                                float* __restrict__ s2,
                                float* __restrict__ s4,
                                float* __restrict__ s8)
{
    int idx = blockIdx.x * blockDim.x + threadIdx.x;
    if (idx >= NROW * 42) return;
    int r = idx / 42, j = idx % 42;
    const float* p = h + (size_t)r * L_ + j * 8;
    float a0 = 0.5f * (p[0] + p[1]);
    float a1 = 0.5f * (p[2] + p[3]);
    float a2 = 0.5f * (p[4] + p[5]);
    float a3 = 0.5f * (p[6] + p[7]);
    float b0 = 0.5f * (a0 + a1);
    float b1 = 0.5f * (a2 + a3);
    float* q2 = s2 + (size_t)r * 168 + j * 4;
    q2[0] = a0; q2[1] = a1; q2[2] = a2; q2[3] = a3;
    float* q4 = s4 + (size_t)r * 84 + j * 2;
    q4[0] = b0; q4[1] = b1;
    s8[(size_t)r * 42 + j] = 0.5f * (b0 + b1);
}

// ---------------- mixer fp32 GEMM, BM=64 x BN=64 (stages 1-2, K=42) ----------------
template<int ACT>
__global__ void __launch_bounds__(256) gemm_m(
    const float* __restrict__ A, int lda,
    const float* __restrict__ W,
    const float* __restrict__ bias,
    const float* __restrict__ resid,
    float* __restrict__ Cout, int ldc,
    int M, int N, int K)
{
    constexpr int BM = 64, BN = 64, BK = 16, TM = 4, TN = 4;
    __shared__ __align__(16) float As[BK][BM + 4];
    __shared__ __align__(16) float Ws[BK][BN + 4];
    int tid = threadIdx.x;
    int ty = tid >> 4, tx = tid & 15;
    int rowBase = blockIdx.y * BM, colBase = blockIdx.x * BN;
    float acc[TM][TN] = {};

    for (int k0 = 0; k0 < K; k0 += BK) {
        #pragma unroll
        for (int i = 0; i < 4; i++) {
            int idx = tid + 256 * i;
            int m = idx >> 4, kk = idx & 15;
            int gk = k0 + kk;
            int gm = rowBase + m;
            As[kk][m] = (gm < M && gk < K) ? A[(size_t)gm * lda + gk] : 0.f;
            int gn = colBase + m;
            Ws[kk][m] = (gn < N && gk < K) ? W[(size_t)gn * K + gk] : 0.f;
        }
        __syncthreads();
        #pragma unroll
        for (int kk = 0; kk < BK; kk++) {
            float a[TM], bf[TN];
            *(float4*)&a[0]  = *(const float4*)&As[kk][ty * TM];
            *(float4*)&bf[0] = *(const float4*)&Ws[kk][tx * TN];
            #pragma unroll
            for (int i = 0; i < TM; i++)
                #pragma unroll
                for (int j = 0; j < TN; j++)
                    acc[i][j] += a[i] * bf[j];
        }
        __syncthreads();
    }

    #pragma unroll
    for (int i = 0; i < TM; i++) {
        int gm = rowBase + ty * TM + i;
        if (gm >= M) continue;
        #pragma unroll
        for (int j = 0; j < TN; j++) {
            int gn = colBase + tx * TN + j;
            if (gn >= N) continue;
            float v = acc[i][j] + (bias ? bias[gn] : 0.f);
            if (ACT == 1) v = gelu_f(v);
            if (resid) v += resid[(size_t)gm * N + gn];
            Cout[(size_t)gm * ldc + gn] = v;
        }
    }
}

// ---------------- mixer tf32 tensor-core GEMM, BM=64 x BN=64 (stages 3-6) ----------------
template<int ACT>
__global__ void __launch_bounds__(256) gemm_tc_m(
    const float* __restrict__ A, int lda,
    const float* __restrict__ W,
    const float* __restrict__ bias,
    const float* __restrict__ resid,
    float* __restrict__ Cout, int ldc,
    int M, int N, int K)
{
    __shared__ __align__(16) float As[2][64][20];
    __shared__ __align__(16) float Ws[2][64][20];
    int tid = threadIdx.x, lane = tid & 31, warp = tid >> 5;
    int g = lane >> 2, t4 = lane & 3;
    int wm = (warp >> 1) * 16, wn = (warp & 1) * 32;
    int rowBase = blockIdx.y * 64, colBase = blockIdx.x * 64;

    float acc[4][4];
    #pragma unroll
    for (int i = 0; i < 4; i++)
        #pragma unroll
        for (int q = 0; q < 4; q++) acc[i][q] = 0.f;

    auto load_tile = [&](int it, int buf) {
        int k0 = it * 16;
        int r = tid >> 2, j = tid & 3;
        int kf = k0 + j * 4;
        int kok = (kf + 4 <= K);
        int kfc = kok ? kf : 0;
        int gm = rowBase + r;
        int gmc = gm < M ? gm : (M - 1);
        cp_async16(&As[buf][r][j * 4],
                   A + (size_t)gmc * lda + kfc,
                   (gm < M && kok) ? 16 : 0);
        int gn = colBase + r;
        int gnc = gn < N ? gn : (N - 1);
        cp_async16(&Ws[buf][r][j * 4],
                   W + (size_t)gnc * K + kfc,
                   (gn < N && kok) ? 16 : 0);
        cp_commit();
    };

    int NK = (K + 15) >> 4;
    int buf = 0;
    load_tile(0, 0);
    for (int it = 0; it < NK; it++) {
        if (it + 1 < NK) { load_tile(it + 1, buf ^ 1); cp_wait<1>(); }
        else             { cp_wait<0>(); }
        __syncthreads();
        #pragma unroll
        for (int kk = 0; kk < 16; kk += 8) {
            uint32_t afr[4], bfr[4][2];
            afr[0] = f2tf32(As[buf][wm + g    ][kk + t4]);
            afr[1] = f2tf32(As[buf][wm + g + 8][kk + t4]);
            afr[2] = f2tf32(As[buf][wm + g    ][kk + t4 + 4]);
            afr[3] = f2tf32(As[buf][wm + g + 8][kk + t4 + 4]);
            #pragma unroll
            for (int nt = 0; nt < 4; nt++) {
                int cb = wn + nt * 8 + g;
                bfr[nt][0] = f2tf32(Ws[buf][cb][kk + t4]);
                bfr[nt][1] = f2tf32(Ws[buf][cb][kk + t4 + 4]);
            }
            #pragma unroll
            for (int nt = 0; nt < 4; nt++)
                mma_tf32(acc[nt], afr, bfr[nt]);
        }
        __syncthreads();
        buf ^= 1;
    }

    int r0 = rowBase + wm + g;
    int r1 = r0 + 8;
    #pragma unroll
    for (int nt = 0; nt < 4; nt++) {
        int c0 = colBase + wn + nt * 8 + 2 * t4;
        #pragma unroll
        for (int q = 0; q < 2; q++) {
            int gn = c0 + q;
            if (gn >= N) continue;
            if (r0 < M) {
                float v = acc[nt][q] + (bias ? bias[gn] : 0.f);
                if (ACT == 1) v = gelu_f(v);
                if (resid) v += resid[(size_t)r0 * N + gn];
                Cout[(size_t)r0 * ldc + gn] = v;
            }
            if (r1 < M) {
                float v = acc[nt][2 + q] + (bias ? bias[gn] : 0.f);
                if (ACT == 1) v = gelu_f(v);
                if (resid) v += resid[(size_t)r1 * N + gn];
                Cout[(size_t)r1 * ldc + gn] = v;
            }
        }
    }
}

// ---------------- gating ----------------
__global__ void gate_kernel(const float* __restrict__ te,
                            const float* __restrict__ gw,
                            const float* __restrict__ gb,
                            float* __restrict__ gates)
{
    int warp = (blockIdx.x * blockDim.x + threadIdx.x) >> 5;
    int lane = threadIdx.x & 31;
    if (warp >= NROW) return;
    const float* row = te + (size_t)warp * L_;
    float acc[E_] = {0.f, 0.f, 0.f, 0.f};
    for (int l = lane; l < L_; l += 32) {
        float xv = row[l];
        #pragma unroll
        for (int e = 0; e < E_; e++) acc[e] += xv * gw[e * L_ + l];
    }
    #pragma unroll
    for (int off = 16; off; off >>= 1)
        #pragma unroll
        for (int e = 0; e < E_; e++)
            acc[e] += __shfl_xor_sync(0xffffffffu, acc[e], off);
    if (lane == 0) {
        float lg[E_], arr[E_];
        #pragma unroll
        for (int e = 0; e < E_; e++) { lg[e] = acc[e] + gb[e]; arr[e] = lg[e]; }
        #pragma unroll
        for (int i = 0; i < 3; i++)
            #pragma unroll
            for (int j = 0; j < 3; j++)
                if (arr[j] > arr[j + 1]) { float tmp = arr[j]; arr[j] = arr[j + 1]; arr[j + 1] = tmp; }
        float kth = arr[E_ - 2];
        float mx = lg[0];
        #pragma unroll
        for (int e = 1; e < E_; e++) mx = fmaxf(mx, lg[e]);
        float s[E_], ssum = 0.f;
        #pragma unroll
        for (int e = 0; e < E_; e++) { s[e] = expf(lg[e] - mx); ssum += s[e]; }
        #pragma unroll
        for (int e = 0; e < E_; e++) s[e] /= ssum;
        float dec[E_];
        #pragma unroll
        for (int e = 0; e < E_; e++)
            dec[e] = (lg[e] < kth) ? 10.f * logf(s[e] + 1.f) : 10.f * (expf(s[e]) - 1.f);
        float m2 = dec[0];
        #pragma unroll
        for (int e = 1; e < E_; e++) m2 = fmaxf(m2, dec[e]);
        float t2[E_], su = 0.f;
        #pragma unroll
        for (int e = 0; e < E_; e++) { t2[e] = expf(dec[e] - m2); su += t2[e]; }
        #pragma unroll
        for (int e = 0; e < E_; e++) gates[(size_t)warp * E_ + e] = t2[e] / su;
    }
}

// ---------------- fused bn + ddi scan, 16 lanes per row (12 active) ----------------
__global__ void __launch_bounds__(256) ddi_scan2_kernel(
    const float* __restrict__ te,
    const float* __restrict__ ddw,
    const float* __restrict__ ddb,
    const float* __restrict__ n1w,
    const float* __restrict__ n1b,
    const float* __restrict__ agg_w,
    const float* __restrict__ agg_b,
    __half* __restrict__ out)
{
    __shared__ float aw[PATCH * PATCH];
    __shared__ float ab[PATCH];
    for (int i = threadIdx.x; i < PATCH * PATCH; i += blockDim.x) aw[i] = agg_w[i];
    for (int i = threadIdx.x; i < PATCH; i += blockDim.x) ab[i] = agg_b[i];
    __syncthreads();

    int gid  = blockIdx.x * blockDim.x + threadIdx.x;
    int row  = gid >> 4;
    int lp   = gid & 15;
    if (row >= NROW) return;
    int c = row % C_;
    int base16 = (threadIdx.x & 31) & ~15;

    bool act = lp < PATCH;
    int lpc = act ? lp : 0;

    float w1 = n1w[c * PATCH + lpc] * INV_;
    float b1 = n1b[c * PATCH + lpc];

    const float* terow = te + (size_t)row * L_;
    const float* wrow  = ddw + (size_t)c * L_;
    const float* brow  = ddb + (size_t)c * L_;
    __half* orow = out + (size_t)row * L_;

    float prev = terow[lpc] * (wrow[lpc] * INV_) + brow[lpc];
    if (act) orow[lp] = __float2half_rn(prev);

    for (int t = 1; t < L_ / PATCH; t++) {
        float inp = prev * w1 + b1;
        float s = ab[lpc];
        #pragma unroll
        for (int p = 0; p < PATCH; p++) {
            float v = __shfl_sync(0xffffffffu, inp, base16 + p, 32);
            s += v * aw[lpc * PATCH + p];
        }
        float tmp = gelu_f(s);
        int l = t * PATCH + lpc;
        prev = tmp + terow[l] * (wrow[l] * INV_) + brow[l];
        if (act) orow[l] = __float2half_rn(prev);
    }
}

// ---------------- merged prep: f2h(ew1) + repack(ew2) + zero(out) ----------------
#define N_W1 (E_*H_*L_)      // 2752512
#define N_W2 (P_*KTOT)       // 786432
__global__ void prep_kernel(const float* __restrict__ ew1, __half* __restrict__ w1h,
                            const float* __restrict__ ew2, __half* __restrict__ w2p,
                            float* __restrict__ out, int out_n)
{
    int idx = blockIdx.x * blockDim.x + threadIdx.x;
    if (idx < N_W1) {
        w1h[idx] = __float2half_rn(ew1[idx]);
    }
    int i2 = idx - N_W1;
    if (i2 >= 0 && i2 < N_W2) {
        int p = i2 / KTOT;
        int r = i2 % KTOT;
        int e = r / H_, hh = r % H_;
        w2p[i2] = __float2half_rn(ew2[((size_t)e * P_ + p) * H_ + hh]);
    }
    int i3 = idx - N_W1 - N_W2;
    if (i3 >= 0 && i3 < out_n) out[i3] = 0.f;
}

// ---------------- launch ----------------
extern "C" void kernel_launch(void* const* d_in, const int* in_sizes, int n_in,
                              void* d_out, int out_size)
{
    // Map inputs, skipping the scalar 'k' (size 1) wherever it sits.
    const float* in[27];
    int pi = 0;
    for (int i = 0; i < n_in && pi < 27; i++) {
        if (in_sizes[i] == 1) continue;
        in[pi++] = (const float*)d_in[i];
    }
    const float* x    = in[0];
    const float* mdw  = in[1];  const float* mdb  = in[2];
    const float* w1s[3] = { in[3], in[7],  in[11] };
    const float* b1s[3] = { in[4], in[8],  in[12] };
    const float* w2s[3] = { in[5], in[9],  in[13] };
    const float* b2s[3] = { in[6], in[10], in[14] };
    const float* ddw  = in[15]; const float* ddb  = in[16];
    const float* n1w  = in[17]; const float* n1b  = in[18];
    const float* aggw = in[19]; const float* aggb = in[20];
    const float* gw   = in[21]; const float* gb   = in[22];
    const float* ew1  = in[23]; const float* eb1  = in[24];
    const float* ew2  = in[25]; const float* eb2  = in[26];

    float *h, *s2, *s4, *s8, *t, *cur, *te, *gates;
    __half *ddih, *w1h, *hid, *w2p;
    cudaGetSymbolAddress((void**)&h,    g_h);
    cudaGetSymbolAddress((void**)&s2,   g_s2);
    cudaGetSymbolAddress((void**)&s4,   g_s4);
    cudaGetSymbolAddress((void**)&s8,   g_s8);
    cudaGetSymbolAddress((void**)&t,    g_t);
    cudaGetSymbolAddress((void**)&cur,  g_cur);
    cudaGetSymbolAddress((void**)&te,   g_te);
    cudaGetSymbolAddress((void**)&ddih, g_ddih);
    cudaGetSymbolAddress((void**)&w1h,  g_w1h);
    cudaGetSymbolAddress((void**)&gates,g_gates);
    cudaGetSymbolAddress((void**)&hid,  g_hid);
    cudaGetSymbolAddress((void**)&w2p,  g_w2p);

    float* out = (float*)d_out;

    // 0) merged prep (also zeros out)
    {
        int total = N_W1 + N_W2 + out_size;
        prep_kernel<<<(total + 255) / 256, 256>>>(ew1, w1h, ew2, w2p, out, out_size);
    }

    // 1) bn + transpose -> h (B,C,L)
    {
        dim3 tb(32, 8);
        dim3 tg((L_ + 31) / 32, (C_ + 31) / 32, B_);
        bn_transpose_kernel<<<tg, tb>>>(x, mdw, mdb, h);
    }
    // 2) fused pools
    pool_all_kernel<<<(NROW * 42 + 255) / 256, 256>>>(h, s2, s4, s8);

    // 3) mixer: stages 1-2 fp32, stages 3-6 tf32 tensor cores
    auto mgrid = [](int M, int N) { return dim3((N + 63) / 64, (M + 63) / 64); };
    gemm_m<1>   <<<mgrid(NROW, 42), 256>>>(s8, 42, w1s[0], b1s[0], nullptr, t,   42,  NROW, 42,  42);
    gemm_m<0>   <<<mgrid(NROW, 84), 256>>>(t,  42, w2s[0], b2s[0], s4,      cur, 84,  NROW, 84,  42);
    gemm_tc_m<1><<<mgrid(NROW, 84), 256>>>(cur,84, w1s[1], b1s[1], nullptr, t,   84,  NROW, 84,  84);
    gemm_tc_m<0><<<mgrid(NROW,168), 256>>>(t,  84, w2s[1], b2s[1], s2,      cur, 168, NROW, 168, 84);
    gemm_tc_m<1><<<mgrid(NROW,168), 256>>>(cur,168,w1s[2], b1s[2], nullptr, t,   168, NROW, 168, 168);
    gemm_tc_m<0><<<mgrid(NROW,336), 256>>>(t,  168,w2s[2], b2s[2], h,       te,  336, NROW, 336, 168);

    // 4) gating from te
    gate_kernel<<<(NROW * 32 + 255) / 256, 256>>>(te, gw, gb, gates);

    // 5) fused bn + scan (16 lanes/row), emits fp16 ddi
    ddi_scan2_kernel<<<(NROW * 16 + 255) / 256, 256>>>(te, ddw, ddb, n1w, n1b, aggw, aggb, ddih);

    // 6) experts — fp16 m16n8k16, 3-stage pipelines; l2 split-K(16) atomic
    {
        dim3 tg(H_ / 128, (NROW + 127) / 128, E_);
        gemm_f16_l1<<<tg, 256>>>(ddih, w1h, eb1, gates, hid, NROW);
    }
    {
        dim3 tg(1, (NROW + 127) / 128, 16);
        gemm_f16_l2<<<tg, 256>>>(hid, w2p, eb2, gates, out, NROW);
    }
}